// round 16
// baseline (speedup 1.0000x reference)
#include <cuda_runtime.h>
#include <cuda_bf16.h>
#include <math.h>

namespace {

typedef unsigned int uint;

constexpr int NTOK  = 4801;
constexpr int D     = 512;
constexpr int QKVW  = 1536;
constexpr int NSP   = 1200;
constexpr int HALFN = 600;
constexpr int NKEY  = 601;
constexpr int NHEAD = 8;
constexpr int DH    = 64;
constexpr float ASCALE = 0.125f;
constexpr int FF1   = 4096;
constexpr int NPATCH= 4800;
constexpr int NGRP  = 64;
constexpr int CLSB  = 19;

// fp32 buffers
__device__ float g_x  [NTOK * D];
__device__ float g_xn [D];
__device__ float g_qkv[NTOK * QKVW];
__device__ float g_cpart[NHEAD * CLSB * 65];
__device__ float g_b1p[12 * FF1];

// packed bf16x2 hi/lo activations (pair along k)
__device__ uint g_xnH[NTOK * 256],  g_xnL[NTOK * 256];
__device__ uint g_atH[NTOK * 256],  g_atL[NTOK * 256];
__device__ uint g_acH[NTOK * 1024], g_acL[NTOK * 1024];
__device__ uint g_tkH[NPATCH * 384], g_tkL[NPATCH * 384];

// split weights [Kp][N] packed bf16x2 (pair along k), per layer contiguous
__device__ uint g_wqtH[12 * 256 * QKVW], g_wqtL[12 * 256 * QKVW];
__device__ uint g_wqsH[12 * 256 * QKVW], g_wqsL[12 * 256 * QKVW];
__device__ uint g_wotH[12 * 256 * D],    g_wotL[12 * 256 * D];
__device__ uint g_wosH[12 * 256 * D],    g_wosL[12 * 256 * D];
__device__ uint g_w1H [12 * 256 * FF1],  g_w1L [12 * 256 * FF1];   // column-permuted (u,g interleave)
__device__ uint g_w2H [12 * 1024 * D],   g_w2L [12 * 1024 * D];
__device__ uint g_wpH [384 * D],         g_wpL [384 * D];

__device__ __forceinline__ void split2(float x0, float x1, uint& hi, uint& lo) {
    __nv_bfloat16 h0 = __float2bfloat16(x0);
    __nv_bfloat16 h1 = __float2bfloat16(x1);
    __nv_bfloat16 l0 = __float2bfloat16(x0 - __bfloat162float(h0));
    __nv_bfloat16 l1 = __float2bfloat16(x1 - __bfloat162float(h1));
    __nv_bfloat162 H = __nv_bfloat162(h0, h1);
    __nv_bfloat162 L = __nv_bfloat162(l0, l1);
    hi = *reinterpret_cast<uint*>(&H);
    lo = *reinterpret_cast<uint*>(&L);
}

__device__ __forceinline__ void mma_bf16(float* acc, const uint* a, const uint* b) {
    asm volatile(
        "mma.sync.aligned.m16n8k16.row.col.f32.bf16.bf16.f32 "
        "{%0,%1,%2,%3}, {%4,%5,%6,%7}, {%8,%9}, {%0,%1,%2,%3};"
        : "+f"(acc[0]), "+f"(acc[1]), "+f"(acc[2]), "+f"(acc[3])
        : "r"(a[0]), "r"(a[1]), "r"(a[2]), "r"(a[3]), "r"(b[0]), "r"(b[1]));
}

__device__ __forceinline__ void ldsm4(uint& r0, uint& r1, uint& r2, uint& r3, uint addr) {
    asm volatile("ldmatrix.sync.aligned.m8n8.x4.shared.b16 {%0,%1,%2,%3}, [%4];"
                 : "=r"(r0), "=r"(r1), "=r"(r2), "=r"(r3) : "r"(addr));
}

__device__ __forceinline__ uint smem_u32(const void* p) {
    uint a;
    asm("{ .reg .u64 t; cvta.to.shared.u64 t, %1; cvt.u32.u64 %0, t; }" : "=r"(a) : "l"(p));
    return a;
}

// ================= GEMM: 3-stage cp.async, single sync per K-step =================
template <int MT>
struct GemmCfg {
    static constexpr int BM     = 32 * MT;
    static constexpr int OFF_AL = 640 * MT;
    static constexpr int OFF_BH = 1280 * MT;
    static constexpr int OFF_BL = 1280 * MT + 2176;
    static constexpr int STG_U  = 1280 * MT + 4352;
    static constexpr int SMEM   = 3 * STG_U * 4;
};
constexpr int SMEM_G128 = GemmCfg<4>::SMEM;
constexpr int SMEM_G64  = GemmCfg<2>::SMEM;

template <int MT, bool GEGLU>
__global__ __launch_bounds__(256, 2)
void bgemm_kernel(const uint* __restrict__ AH, const uint* __restrict__ AL,
                  const uint* __restrict__ BH, const uint* __restrict__ BL,
                  const float* __restrict__ bias, const float* __restrict__ resid,
                  float* __restrict__ C, uint* __restrict__ CH, uint* __restrict__ CL,
                  int M, int N, int Kp)
{
    using CF = GemmCfg<MT>;
    extern __shared__ uint dsm[];
    const uint sbase = smem_u32(dsm);
    const int tid  = threadIdx.x;
    const int lane = tid & 31;
    const int warp = tid >> 5;
    const int grp  = lane >> 2;
    const int qid  = lane & 3;
    const int wm   = (warp & 1) * (MT * 16);
    const int wn   = (warp >> 1) * 32;
    const int row0 = blockIdx.y * CF::BM;
    const int col0 = blockIdx.x * 128;

    float acc[MT][4][4];
#pragma unroll
    for (int mt = 0; mt < MT; mt++)
#pragma unroll
        for (int nt = 0; nt < 4; nt++)
#pragma unroll
            for (int e = 0; e < 4; e++) acc[mt][nt][e] = 0.f;

    auto load_stage = [&](int st, int kp0) {
        uint base = sbase + st * (CF::STG_U * 4);
#pragma unroll
        for (int u = 0; u < MT / 2; u++) {
            int idx = tid + u * 256;
            int r = idx >> 2, c4 = idx & 3;
            int gr = row0 + r;
            int sz = (gr < M) ? 16 : 0;
            size_t goff = (size_t)(gr < M ? gr : 0) * Kp + kp0 + c4 * 4;
            uint d = base + (r * 20 + c4 * 4) * 4;
            asm volatile("cp.async.cg.shared.global [%0], [%1], 16, %2;"
                         :: "r"(d), "l"(AH + goff), "r"(sz));
            asm volatile("cp.async.cg.shared.global [%0], [%1], 16, %2;"
                         :: "r"(d + CF::OFF_AL * 4), "l"(AL + goff), "r"(sz));
        }
#pragma unroll
        for (int u = 0; u < 2; u++) {
            int idx = tid + u * 256;
            int kr = idx >> 5, c4 = idx & 31;
            size_t goff = (size_t)(kp0 + kr) * N + col0 + c4 * 4;
            uint d = base + (CF::OFF_BH + kr * 136 + c4 * 4) * 4;
            asm volatile("cp.async.cg.shared.global [%0], [%1], 16;"
                         :: "r"(d), "l"(BH + goff));
            asm volatile("cp.async.cg.shared.global [%0], [%1], 16;"
                         :: "r"(d + (CF::OFF_BL - CF::OFF_BH) * 4), "l"(BL + goff));
        }
    };

    auto compute = [&](int st) {
        const uint* AsH = dsm + st * CF::STG_U;
        const uint* AsL = AsH + CF::OFF_AL;
        const uint* BsH = dsm + st * CF::STG_U + CF::OFF_BH;
        const uint* BsL = dsm + st * CF::STG_U + CF::OFF_BL;
#pragma unroll
        for (int kk = 0; kk < 2; kk++) {
            uint bhf[4][2], blf[4][2];
#pragma unroll
            for (int nt = 0; nt < 4; nt++) {
                int c = wn + nt * 8 + grp;
                bhf[nt][0] = BsH[(kk * 8 + qid    ) * 136 + c];
                bhf[nt][1] = BsH[(kk * 8 + qid + 4) * 136 + c];
                blf[nt][0] = BsL[(kk * 8 + qid    ) * 136 + c];
                blf[nt][1] = BsL[(kk * 8 + qid + 4) * 136 + c];
            }
#pragma unroll
            for (int mt = 0; mt < MT; mt++) {
                int r = wm + mt * 16;
                uint ah[4], al[4];
                ah[0] = AsH[(r + grp    ) * 20 + kk * 8 + qid    ];
                ah[1] = AsH[(r + grp + 8) * 20 + kk * 8 + qid    ];
                ah[2] = AsH[(r + grp    ) * 20 + kk * 8 + qid + 4];
                ah[3] = AsH[(r + grp + 8) * 20 + kk * 8 + qid + 4];
                al[0] = AsL[(r + grp    ) * 20 + kk * 8 + qid    ];
                al[1] = AsL[(r + grp + 8) * 20 + kk * 8 + qid    ];
                al[2] = AsL[(r + grp    ) * 20 + kk * 8 + qid + 4];
                al[3] = AsL[(r + grp + 8) * 20 + kk * 8 + qid + 4];
                // term-major: same-acc revisits separated by 4 independent MMAs;
                // per-acc term order (lo*hi, hi*lo, hi*hi) preserved -> identical numerics
#pragma unroll
                for (int nt = 0; nt < 4; nt++) mma_bf16(acc[mt][nt], al, bhf[nt]);
#pragma unroll
                for (int nt = 0; nt < 4; nt++) mma_bf16(acc[mt][nt], ah, blf[nt]);
#pragma unroll
                for (int nt = 0; nt < 4; nt++) mma_bf16(acc[mt][nt], ah, bhf[nt]);
            }
        }
    };

    const int nch = Kp / 16;
    load_stage(0, 0);
    asm volatile("cp.async.commit_group;" ::: "memory");
    load_stage(1, 16);
    asm volatile("cp.async.commit_group;" ::: "memory");
    for (int ch = 0; ch < nch; ch++) {
        if (ch + 1 < nch) asm volatile("cp.async.wait_group 1;" ::: "memory");
        else              asm volatile("cp.async.wait_group 0;" ::: "memory");
        __syncthreads();
        int nx = ch + 2;
        if (nx < nch) {
            load_stage(nx % 3, nx * 16);
            asm volatile("cp.async.commit_group;" ::: "memory");
        }
        compute(ch % 3);
    }

#pragma unroll
    for (int mt = 0; mt < MT; mt++) {
#pragma unroll
        for (int e2 = 0; e2 < 2; e2++) {
            int gr = row0 + wm + mt * 16 + grp + e2 * 8;
#pragma unroll
            for (int nt = 0; nt < 4; nt++) {
                int gc = col0 + wn + nt * 8 + qid * 2;
                float v0 = acc[mt][nt][e2 * 2 + 0];
                float v1 = acc[mt][nt][e2 * 2 + 1];
                if (GEGLU) {
                    v0 += bias[gc];
                    v1 += bias[gc + 1];
                    float ge = 0.5f * v1 * (1.f + erff(v1 * 0.70710678118654752f));
                    float act = v0 * ge;
                    float partner = __shfl_xor_sync(0xffffffffu, act, 1);
                    if (gr < M && (qid & 1) == 0) {
                        split2(act, partner,
                               CH[(size_t)gr * (N >> 2) + (gc >> 2)],
                               CL[(size_t)gr * (N >> 2) + (gc >> 2)]);
                    }
                } else {
                    if (gr < M) {
                        if (bias)  { v0 += bias[gc]; v1 += bias[gc + 1]; }
                        if (resid) {
                            v0 += resid[(size_t)gr * N + gc];
                            v1 += resid[(size_t)gr * N + gc + 1];
                        }
                        C[(size_t)gr * N + gc]     = v0;
                        C[(size_t)gr * N + gc + 1] = v1;
                    }
                }
            }
        }
    }
}

// ---------------------------------------------------------------- weight split prep
__global__ void split_w_kernel(const float* __restrict__ W, uint* __restrict__ H,
                               uint* __restrict__ L, int N, long long total)
{
    long long idx = (long long)blockIdx.x * blockDim.x + threadIdx.x;
    if (idx >= total) return;
    long long kp = idx / N;
    int n = (int)(idx - kp * N);
    float x0 = W[(size_t)(2 * kp) * N + n];
    float x1 = W[(size_t)(2 * kp + 1) * N + n];
    split2(x0, x1, H[idx], L[idx]);
}

__global__ void split_w1_kernel(const float* __restrict__ W, uint* __restrict__ H,
                                uint* __restrict__ L, long long total)
{
    long long idx = (long long)blockIdx.x * blockDim.x + threadIdx.x;
    if (idx >= total) return;
    long long kp = idx / FF1;
    int n = (int)(idx - kp * FF1);
    int oc = (n & 1) ? (2048 + (n >> 1)) : (n >> 1);
    float x0 = W[(size_t)(2 * kp) * FF1 + oc];
    float x1 = W[(size_t)(2 * kp + 1) * FF1 + oc];
    split2(x0, x1, H[idx], L[idx]);
}

__global__ void permute_b1_kernel(const float* __restrict__ B, float* __restrict__ O)
{
    int idx = blockIdx.x * blockDim.x + threadIdx.x;
    if (idx >= 12 * FF1) return;
    int l = idx >> 12, n = idx & 4095;
    int oc = (n & 1) ? (2048 + (n >> 1)) : (n >> 1);
    O[idx] = B[l * FF1 + oc];
}

// ---------------------------------------------------------------- patchify (packed out)
__global__ void patchify_kernel(const float* __restrict__ video,
                                uint* __restrict__ tH, uint* __restrict__ tL)
{
    int idx = blockIdx.x * blockDim.x + threadIdx.x;
    if (idx >= NPATCH * 384) return;
    int t = idx / 384, pp = idx % 384;
    int side = t / 2400;
    int r = t % 2400;
    int f = r / 600;
    int rr = r % 600;
    int ph = rr / 20;
    int pw = rr % 20;
    float v[2];
#pragma unroll
    for (int e = 0; e < 2; e++) {
        int pd = pp * 2 + e;
        int p1 = pd / 48;
        int rem = pd % 48;
        int p2 = rem / 3;
        int c  = rem % 3;
        int row = ph * 16 + p1;
        int col = side * 320 + pw * 16 + p2;
        v[e] = video[(((size_t)f * 3 + c) * 480 + row) * 640 + col];
    }
    split2(v[0], v[1], tH[idx], tL[idx]);
}

__global__ void addpos_kernel(float* __restrict__ x, const float* __restrict__ cls,
                              const float* __restrict__ pos)
{
    int idx = blockIdx.x * blockDim.x + threadIdx.x;
    if (idx >= NTOK * D) return;
    if (idx < D) x[idx] = cls[idx] + pos[idx];
    else         x[idx] += pos[idx];
}

// ---------------------------------------------------------------- LayerNorm (warp-per-row, packed out)
__global__ __launch_bounds__(256)
void layernorm_pack_kernel(const float* __restrict__ x, const float* __restrict__ g,
                           const float* __restrict__ b,
                           uint* __restrict__ oH, uint* __restrict__ oL)
{
    int warp = threadIdx.x >> 5, lane = threadIdx.x & 31;
    int row = blockIdx.x * 8 + warp;
    if (row >= NTOK) return;
    const float* xr = x + (size_t)row * D;

    float4 a[4];
#pragma unroll
    for (int k = 0; k < 4; k++)
        a[k] = *reinterpret_cast<const float4*>(xr + (k * 32 + lane) * 4);

    float s = 0.f;
#pragma unroll
    for (int k = 0; k < 4; k++) s += a[k].x + a[k].y + a[k].z + a[k].w;
#pragma unroll
    for (int o = 16; o; o >>= 1) s += __shfl_xor_sync(0xffffffffu, s, o);
    float mu = s * (1.f / 512.f);

    float v = 0.f;
#pragma unroll
    for (int k = 0; k < 4; k++) {
        float d0 = a[k].x - mu, d1 = a[k].y - mu, d2 = a[k].z - mu, d3 = a[k].w - mu;
        v += d0 * d0 + d1 * d1 + d2 * d2 + d3 * d3;
    }
#pragma unroll
    for (int o = 16; o; o >>= 1) v += __shfl_xor_sync(0xffffffffu, v, o);
    float rstd = rsqrtf(v * (1.f / 512.f) + 1e-5f);

#pragma unroll
    for (int k = 0; k < 4; k++) {
        int e4 = (k * 32 + lane) * 4;
        float4 gv = *reinterpret_cast<const float4*>(g + e4);
        float4 bv = *reinterpret_cast<const float4*>(b + e4);
        float y0 = (a[k].x - mu) * rstd * gv.x + bv.x;
        float y1 = (a[k].y - mu) * rstd * gv.y + bv.y;
        float y2 = (a[k].z - mu) * rstd * gv.z + bv.z;
        float y3 = (a[k].w - mu) * rstd * gv.w + bv.w;
        uint h0, l0, h1, l1;
        split2(y0, y1, h0, l0);
        split2(y2, y3, h1, l1);
        uint2 H = make_uint2(h0, h1), L = make_uint2(l0, l1);
        *reinterpret_cast<uint2*>(oH + (size_t)row * 256 + (e4 >> 1)) = H;
        *reinterpret_cast<uint2*>(oL + (size_t)row * 256 + (e4 >> 1)) = L;
    }
}

// ---------------------------------------------------------------- final LN (fp32, row 0)
__global__ void layernorm_kernel(const float* __restrict__ x, const float* __restrict__ g,
                                 const float* __restrict__ b, float* __restrict__ out)
{
    int tid = threadIdx.x;
    float x0 = x[tid], x1 = x[tid + 256];
    __shared__ float red[8];

    float s = x0 + x1;
#pragma unroll
    for (int o = 16; o; o >>= 1) s += __shfl_xor_sync(0xffffffffu, s, o);
    if ((tid & 31) == 0) red[tid >> 5] = s;
    __syncthreads();
    if (tid == 0) { float t = 0; for (int i = 0; i < 8; i++) t += red[i]; red[0] = t; }
    __syncthreads();
    float mu = red[0] * (1.f / 512.f);
    __syncthreads();

    float d0 = x0 - mu, d1 = x1 - mu;
    float v = d0 * d0 + d1 * d1;
#pragma unroll
    for (int o = 16; o; o >>= 1) v += __shfl_xor_sync(0xffffffffu, v, o);
    if ((tid & 31) == 0) red[tid >> 5] = v;
    __syncthreads();
    if (tid == 0) { float t = 0; for (int i = 0; i < 8; i++) t += red[i]; red[0] = t; }
    __syncthreads();
    float rstd = rsqrtf(red[0] * (1.f / 512.f) + 1e-5f);

    out[tid]       = d0 * rstd * g[tid] + b[tid];
    out[tid + 256] = d1 * rstd * g[tid + 256] + b[tid + 256];
}

// ---------------------------------------------------------------- cls attention phase 1 (split-K)
__global__ void cls_attn_p1(const float* __restrict__ qkv, float* __restrict__ cpart)
{
    int h = blockIdx.x, blk = blockIdx.y;
    int tid = threadIdx.x;
    __shared__ float qs[DH];
    __shared__ float sl[256];
    __shared__ float red[8];
    __shared__ float part[4][DH];

    if (tid < DH) qs[tid] = ASCALE * qkv[h * DH + tid];
    __syncthreads();

    int tok = blk * 256 + tid;
    float e = 0.f;
    if (tok < NTOK) {
        const float* kb = qkv + (size_t)tok * QKVW + 512 + h * DH;
        float s = 0.f;
#pragma unroll
        for (int d4 = 0; d4 < DH; d4 += 4) {
            float4 kv = *reinterpret_cast<const float4*>(kb + d4);
            s += qs[d4] * kv.x + qs[d4 + 1] * kv.y + qs[d4 + 2] * kv.z + qs[d4 + 3] * kv.w;
        }
        e = __expf(s);
    }
    sl[tid] = e;
    float esum = e;
#pragma unroll
    for (int o = 16; o; o >>= 1) esum += __shfl_xor_sync(0xffffffffu, esum, o);
    if ((tid & 31) == 0) red[tid >> 5] = esum;
    __syncthreads();

    int gi = tid >> 6, d = tid & 63;
    float acc = 0.f;
    for (int jj = gi; jj < 256; jj += 4) {
        int t2 = blk * 256 + jj;
        if (t2 < NTOK) acc += sl[jj] * qkv[(size_t)t2 * QKVW + 1024 + h * DH + d];
    }
    part[gi][d] = acc;
    __syncthreads();

    if (tid < DH)
        cpart[(h * CLSB + blk) * 65 + tid] =
            part[0][tid] + part[1][tid] + part[2][tid] + part[3][tid];
    if (tid == 0) {
        float t = 0.f;
        for (int i = 0; i < 8; i++) t += red[i];
        cpart[(h * CLSB + blk) * 65 + 64] = t;
    }
}

// ---------------------------------------------------------------- cls attention phase 2
__global__ void cls_attn_p2(const float* __restrict__ cpart,
                            uint* __restrict__ aH, uint* __restrict__ aL)
{
    int h = blockIdx.x;
    int tid = threadIdx.x;  // 64
    __shared__ float o[DH];
    float acc = 0.f, den = 0.f;
    for (int b = 0; b < CLSB; b++) {
        acc += cpart[(h * CLSB + b) * 65 + tid];
        den += cpart[(h * CLSB + b) * 65 + 64];
    }
    o[tid] = acc / den;
    __syncthreads();
    if (tid < 32) split2(o[2 * tid], o[2 * tid + 1], aH[h * 32 + tid], aL[h * 32 + tid]);
}

// ---------------------------------------------------------------- time attention
__global__ void time_attn_kernel(const float* __restrict__ qkv,
                                 uint* __restrict__ aH, uint* __restrict__ aL)
{
    int w = (blockIdx.x * blockDim.x + threadIdx.x) >> 5;
    int lane = threadIdx.x & 31;
    if (w >= NHEAD * NSP * 4) return;
    int h = w / (NSP * 4);
    int rem = w % (NSP * 4);
    int nn = rem / 4;
    int f  = rem % 4;
    int qt = 1 + f * NSP + nn;

    const float* qb = qkv + (size_t)qt * QKVW + h * DH;
    float q0 = ASCALE * qb[2 * lane], q1 = ASCALE * qb[2 * lane + 1];

    int kt[5] = {0, 1 + nn, 1 + NSP + nn, 1 + 2 * NSP + nn, 1 + 3 * NSP + nn};
    float lg[5];
#pragma unroll
    for (int j = 0; j < 5; j++) {
        const float* kb = qkv + (size_t)kt[j] * QKVW + 512 + h * DH;
        float p = q0 * kb[2 * lane] + q1 * kb[2 * lane + 1];
#pragma unroll
        for (int o = 16; o; o >>= 1) p += __shfl_xor_sync(0xffffffffu, p, o);
        lg[j] = p;
    }
    float m = lg[0];
#pragma unroll
    for (int j = 1; j < 5; j++) m = fmaxf(m, lg[j]);
    float e[5], s = 0.f;
#pragma unroll
    for (int j = 0; j < 5; j++) { e[j] = expf(lg[j] - m); s += e[j]; }
    float inv = 1.f / s;

    float o0 = 0.f, o1 = 0.f;
#pragma unroll
    for (int j = 0; j < 5; j++) {
        const float* vb = qkv + (size_t)kt[j] * QKVW + 1024 + h * DH;
        float p = e[j] * inv;
        o0 += p * vb[2 * lane];
        o1 += p * vb[2 * lane + 1];
    }
    split2(o0, o1, aH[(size_t)qt * 256 + h * 32 + lane], aL[(size_t)qt * 256 + h * 32 + lane]);
}

// ---------------------------------------------------------------- fused space attention (flash)
constexpr uint OQ_H = 0,     OQ_L = 2304;
constexpr uint OK_H = 4608,  OK_L = 6912;
constexpr uint OV_H = 9216,  OV_L = 11520;
constexpr uint OP_H = 13824, OP_L = 16128;
constexpr uint ODEN = 18432;
constexpr int  SMEM_F = (18432 + 128) * 4;

__global__ __launch_bounds__(256)
void space_flash_kernel(const float* __restrict__ qkv,
                        uint* __restrict__ aH, uint* __restrict__ aL)
{
    extern __shared__ uint sm[];
    float* den = reinterpret_cast<float*>(sm + ODEN);
    const uint sbase = smem_u32(sm);

    int g = blockIdx.y;
    int h = g >> 3, f = (g >> 1) & 3, half = g & 1;
    int i0 = blockIdx.x * 64;
    int tid = threadIdx.x;
    int lane = tid & 31, warp = tid >> 5;
    int grp = lane >> 2, qid = lane & 3;
    int wm = (warp & 3) * 16;
    int wn = (warp >> 2) * 32;
    const int subA_row = ((lane >> 3) & 1) * 8 + (lane & 7);
    const int subA_col = ((lane >> 4) & 1) * 4;
    const int subB_row = ((lane >> 4) & 1) * 8 + (lane & 7);
    const int subB_col = ((lane >> 3) & 1) * 4;
    const int kbase = 1 + f * NSP + (1 - half) * HALFN;

#pragma unroll
    for (int u = 0; u < 8; u++) {
        int idx = tid + u * 256;
        int r = idx >> 5, dp = idx & 31;
        int i = i0 + r;
        float2 qv = make_float2(0.f, 0.f);
        if (i < HALFN) {
            int qt = 1 + f * NSP + half * HALFN + i;
            qv = *reinterpret_cast<const float2*>(qkv + (size_t)qt * QKVW + h * DH + 2 * dp);
        }
        split2(ASCALE * qv.x, ASCALE * qv.y, sm[OQ_H + r * 36 + dp], sm[OQ_L + r * 36 + dp]);
    }

    float oacc[4][4];
#pragma unroll
    for (int nt = 0; nt < 4; nt++)
#pragma unroll
        for (int e = 0; e < 4; e++) oacc[nt][e] = 0.f;
    float dsum[2] = {0.f, 0.f};

    for (int jt = 0; jt < 10; jt++) {
        int j0 = jt * 64;
#pragma unroll
        for (int u = 0; u < 8; u++) {
            int idx = tid + u * 256;
            int r = idx >> 5, dp = idx & 31;
            int j = j0 + r;
            float2 kv = make_float2(0.f, 0.f);
            if (j < NKEY) {
                int kt = j ? (kbase + j - 1) : 0;
                kv = *reinterpret_cast<const float2*>(qkv + (size_t)kt * QKVW + 512 + h * DH + 2 * dp);
            }
            split2(kv.x, kv.y, sm[OK_H + r * 36 + dp], sm[OK_L + r * 36 + dp]);
        }
#pragma unroll
        for (int u = 0; u < 8; u++) {
            int idx = tid + u * 256;
            int d = idx & 63, jp = idx >> 6;
            int j1 = j0 + 2 * jp, j2 = j1 + 1;
            float v0 = 0.f, v1 = 0.f;
            if (j1 < NKEY) {
                int kt = j1 ? (kbase + j1 - 1) : 0;
                v0 = qkv[(size_t)kt * QKVW + 1024 + h * DH + d];
            }
            if (j2 < NKEY) {
                int kt = kbase + j2 - 1;
                v1 = qkv[(size_t)kt * QKVW + 1024 + h * DH + d];
            }
            split2(v0, v1, sm[OV_H + d * 36 + jp], sm[OV_L + d * 36 + jp]);
        }
        __syncthreads();

        float facc[4][4];
#pragma unroll
        for (int nt = 0; nt < 4; nt++)
#pragma unroll
            for (int e = 0; e < 4; e++) facc[nt][e] = 0.f;
#pragma unroll
        for (int kk = 0; kk < 4; kk++) {
            uint ah[4], al[4];
            uint aaddr = sbase + (OQ_H + (wm + subA_row) * 36 + kk * 8 + subA_col) * 4;
            ldsm4(ah[0], ah[1], ah[2], ah[3], aaddr);
            ldsm4(al[0], al[1], al[2], al[3], aaddr + (OQ_L - OQ_H) * 4);
            uint bh[4][2], bl[4][2];
#pragma unroll
            for (int p = 0; p < 2; p++) {
                uint baddr = sbase + (OK_H + (wn + p * 16 + subB_row) * 36 + kk * 8 + subB_col) * 4;
                ldsm4(bh[2 * p][0], bh[2 * p][1], bh[2 * p + 1][0], bh[2 * p + 1][1], baddr);
                ldsm4(bl[2 * p][0], bl[2 * p][1], bl[2 * p + 1][0], bl[2 * p + 1][1],
                      baddr + (OK_L - OK_H) * 4);
            }
            // term-major reorder (numerics preserved per-acc)
#pragma unroll
            for (int nt = 0; nt < 4; nt++) mma_bf16(facc[nt], al, bh[nt]);
#pragma unroll
            for (int nt = 0; nt < 4; nt++) mma_bf16(facc[nt], ah, bl[nt]);
#pragma unroll
            for (int nt = 0; nt < 4; nt++) mma_bf16(facc[nt], ah, bh[nt]);
        }
#pragma unroll
        for (int e2 = 0; e2 < 2; e2++) {
            int row = wm + grp + e2 * 8;
#pragma unroll
            for (int nt = 0; nt < 4; nt++) {
                int jl = wn + nt * 8 + qid * 2;
                int jg = j0 + jl;
                float p0 = (jg     < NKEY) ? __expf(facc[nt][e2 * 2 + 0]) : 0.f;
                float p1 = (jg + 1 < NKEY) ? __expf(facc[nt][e2 * 2 + 1]) : 0.f;
                dsum[e2] += p0 + p1;
                split2(p0, p1, sm[OP_H + row * 36 + (jl >> 1)], sm[OP_L + row * 36 + (jl >> 1)]);
            }
        }
        __syncthreads();

#pragma unroll
        for (int kk = 0; kk < 4; kk++) {
            uint ah[4], al[4];
            uint aaddr = sbase + (OP_H + (wm + subA_row) * 36 + kk * 8 + subA_col) * 4;
            ldsm4(ah[0], ah[1], ah[2], ah[3], aaddr);
            ldsm4(al[0], al[1], al[2], al[3], aaddr + (OP_L - OP_H) * 4);
            uint bh[4][2], bl[4][2];
#pragma unroll
            for (int p = 0; p < 2; p++) {
                uint baddr = sbase + (OV_H + (wn + p * 16 + subB_row) * 36 + kk * 8 + subB_col) * 4;
                ldsm4(bh[2 * p][0], bh[2 * p][1], bh[2 * p + 1][0], bh[2 * p + 1][1], baddr);
                ldsm4(bl[2 * p][0], bl[2 * p][1], bl[2 * p + 1][0], bl[2 * p + 1][1],
                      baddr + (OV_L - OV_H) * 4);
            }
#pragma unroll
            for (int nt = 0; nt < 4; nt++) mma_bf16(oacc[nt], al, bh[nt]);
#pragma unroll
            for (int nt = 0; nt < 4; nt++) mma_bf16(oacc[nt], ah, bl[nt]);
#pragma unroll
            for (int nt = 0; nt < 4; nt++) mma_bf16(oacc[nt], ah, bh[nt]);
        }
        __syncthreads();
    }

#pragma unroll
    for (int e2 = 0; e2 < 2; e2++) {
        float v = dsum[e2];
        v += __shfl_xor_sync(0xffffffffu, v, 1);
        v += __shfl_xor_sync(0xffffffffu, v, 2);
        if (qid == 0) den[(warp >> 2) * 64 + wm + grp + e2 * 8] = v;
    }
    __syncthreads();

#pragma unroll
    for (int e2 = 0; e2 < 2; e2++) {
        int row = wm + grp + e2 * 8;
        int i = i0 + row;
        if (i >= HALFN) continue;
        float inv = 1.f / (den[row] + den[64 + row]);
        int qt = 1 + f * NSP + half * HALFN + i;
#pragma unroll
        for (int nt = 0; nt < 4; nt++) {
            int dp = ((wn + nt * 8) >> 1) + qid;
            split2(oacc[nt][e2 * 2 + 0] * inv, oacc[nt][e2 * 2 + 1] * inv,
                   aH[(size_t)qt * 256 + h * 32 + dp], aL[(size_t)qt * 256 + h * 32 + dp]);
        }
    }
}

// ---------------------------------------------------------------- head
__global__ void head_kernel(const float* __restrict__ xn, const float* __restrict__ ow,
                            const float* __restrict__ ob, float* __restrict__ out)
{
    int tid = threadIdx.x;
    if (tid >= 60) return;
    float s = ob[tid];
    for (int d = 0; d < D; d++) s += xn[d] * ow[d * 60 + tid];
    out[tid] = s;
}

}  // namespace

extern "C" void kernel_launch(void* const* d_in, const int* in_sizes, int n_in,
                              void* d_out, int out_size)
{
    const float* video   = (const float*)d_in[0];
    const float* patch_w = (const float*)d_in[1];
    const float* patch_b = (const float*)d_in[2];
    const float* pos_emb = (const float*)d_in[3];
    const float* cls_tok = (const float*)d_in[4];
    const float* t_ln_g  = (const float*)d_in[5];
    const float* t_ln_b  = (const float*)d_in[6];
    const float* t_qkv_w = (const float*)d_in[7];
    const float* t_out_w = (const float*)d_in[8];
    const float* t_out_b = (const float*)d_in[9];
    const float* s_ln_g  = (const float*)d_in[10];
    const float* s_ln_b  = (const float*)d_in[11];
    const float* s_qkv_w = (const float*)d_in[12];
    const float* s_out_w = (const float*)d_in[13];
    const float* s_out_b = (const float*)d_in[14];
    const float* f_ln_g  = (const float*)d_in[15];
    const float* f_ln_b  = (const float*)d_in[16];
    const float* f_w1    = (const float*)d_in[17];
    const float* f_b1    = (const float*)d_in[18];
    const float* f_w2    = (const float*)d_in[19];
    const float* f_b2    = (const float*)d_in[20];
    const float* o_ln_g  = (const float*)d_in[21];
    const float* o_ln_b  = (const float*)d_in[22];
    const float* o_w     = (const float*)d_in[23];
    const float* o_b     = (const float*)d_in[24];
    float* out = (float*)d_out;

    cudaFuncSetAttribute(bgemm_kernel<4, false>, cudaFuncAttributeMaxDynamicSharedMemorySize, SMEM_G128);
    cudaFuncSetAttribute(bgemm_kernel<4, true>,  cudaFuncAttributeMaxDynamicSharedMemorySize, SMEM_G128);
    cudaFuncSetAttribute(bgemm_kernel<2, false>, cudaFuncAttributeMaxDynamicSharedMemorySize, SMEM_G64);
    cudaFuncSetAttribute(space_flash_kernel, cudaFuncAttributeMaxDynamicSharedMemorySize, SMEM_F);

    float *x, *xn, *qkv, *cpart, *b1p;
    cudaGetSymbolAddress((void**)&x,     g_x);
    cudaGetSymbolAddress((void**)&xn,    g_xn);
    cudaGetSymbolAddress((void**)&qkv,   g_qkv);
    cudaGetSymbolAddress((void**)&cpart, g_cpart);
    cudaGetSymbolAddress((void**)&b1p,   g_b1p);

    uint *xnH, *xnL, *atH, *atL, *acH, *acL, *tkH, *tkL;
    cudaGetSymbolAddress((void**)&xnH, g_xnH); cudaGetSymbolAddress((void**)&xnL, g_xnL);
    cudaGetSymbolAddress((void**)&atH, g_atH); cudaGetSymbolAddress((void**)&atL, g_atL);
    cudaGetSymbolAddress((void**)&acH, g_acH); cudaGetSymbolAddress((void**)&acL, g_acL);
    cudaGetSymbolAddress((void**)&tkH, g_tkH); cudaGetSymbolAddress((void**)&tkL, g_tkL);

    uint *wqtH, *wqtL, *wqsH, *wqsL, *wotH, *wotL, *wosH, *wosL, *w1H, *w1L, *w2H, *w2L, *wpH, *wpL;
    cudaGetSymbolAddress((void**)&wqtH, g_wqtH); cudaGetSymbolAddress((void**)&wqtL, g_wqtL);
    cudaGetSymbolAddress((void**)&wqsH, g_wqsH); cudaGetSymbolAddress((void**)&wqsL, g_wqsL);
    cudaGetSymbolAddress((void**)&wotH, g_wotH); cudaGetSymbolAddress((void**)&wotL, g_wotL);
    cudaGetSymbolAddress((void**)&wosH, g_wosH); cudaGetSymbolAddress((void**)&wosL, g_wosL);
    cudaGetSymbolAddress((void**)&w1H,  g_w1H);  cudaGetSymbolAddress((void**)&w1L,  g_w1L);
    cudaGetSymbolAddress((void**)&w2H,  g_w2H);  cudaGetSymbolAddress((void**)&w2L,  g_w2L);
    cudaGetSymbolAddress((void**)&wpH,  g_wpH);  cudaGetSymbolAddress((void**)&wpL,  g_wpL);

    auto splitw = [&](const float* W, uint* H, uint* L, long long Kp_total, int N) {
        long long total = Kp_total * N;
        int blocks = (int)((total + 255) / 256);
        split_w_kernel<<<blocks, 256>>>(W, H, L, N, total);
    };

    splitw(t_qkv_w, wqtH, wqtL, 12LL * 256, QKVW);
    splitw(s_qkv_w, wqsH, wqsL, 12LL * 256, QKVW);
    splitw(t_out_w, wotH, wotL, 12LL * 256, D);
    splitw(s_out_w, wosH, wosL, 12LL * 256, D);
    {
        long long total = 12LL * 256 * FF1;
        split_w1_kernel<<<(int)((total + 255) / 256), 256>>>(f_w1, w1H, w1L, total);
        permute_b1_kernel<<<(12 * FF1 + 255) / 256, 256>>>(f_b1, b1p);
    }
    splitw(f_w2,    w2H,  w2L,  12LL * 1024, D);
    splitw(patch_w, wpH,  wpL,  384LL, D);

    auto gemm128 = [&](const uint* AH, const uint* AL, const uint* BH, const uint* BL,
                       const float* bias, const float* resid, float* C, int M, int N, int Kp) {
        dim3 grid(N / 128, (M + 127) / 128);
        bgemm_kernel<4, false><<<grid, 256, SMEM_G128>>>(AH, AL, BH, BL, bias, resid, C,
                                                         nullptr, nullptr, M, N, Kp);
    };
    auto gemm64 = [&](const uint* AH, const uint* AL, const uint* BH, const uint* BL,
                      const float* bias, const float* resid, float* C, int M, int N, int Kp) {
        dim3 grid(N / 128, (M + 63) / 64);
        bgemm_kernel<2, false><<<grid, 256, SMEM_G64>>>(AH, AL, BH, BL, bias, resid, C,
                                                        nullptr, nullptr, M, N, Kp);
    };
    auto gemm_geglu = [&](const uint* AH, const uint* AL, const uint* BH, const uint* BL,
                          const float* bias, uint* CH, uint* CL, int M, int N, int Kp) {
        dim3 grid(N / 128, (M + 127) / 128);
        bgemm_kernel<4, true><<<grid, 256, SMEM_G128>>>(AH, AL, BH, BL, bias, nullptr, nullptr,
                                                        CH, CL, M, N, Kp);
    };

    // ---- patch embed + pos + cls ----
    patchify_kernel<<<(NPATCH * 384 + 255) / 256, 256>>>(video, tkH, tkL);
    gemm64(tkH, tkL, wpH, wpL, patch_b, nullptr, x + D, NPATCH, D, 384);
    addpos_kernel<<<(NTOK * D + 255) / 256, 256>>>(x, cls_tok, pos_emb);

    for (int i = 0; i < 12; i++) {
        // ---------------- time attention ----------------
        layernorm_pack_kernel<<<(NTOK + 7) / 8, 256>>>(x, t_ln_g + i * D, t_ln_b + i * D, xnH, xnL);
        gemm128(xnH, xnL, wqtH + (size_t)i * 256 * QKVW, wqtL + (size_t)i * 256 * QKVW,
                nullptr, nullptr, qkv, NTOK, QKVW, 256);
        cls_attn_p1<<<dim3(NHEAD, CLSB), 256>>>(qkv, cpart);
        cls_attn_p2<<<NHEAD, 64>>>(cpart, atH, atL);
        time_attn_kernel<<<(NHEAD * NSP * 4 * 32 + 255) / 256, 256>>>(qkv, atH, atL);
        gemm64(atH, atL, wotH + (size_t)i * 256 * D, wotL + (size_t)i * 256 * D,
               t_out_b + i * D, x, x, NTOK, D, 256);

        // ---------------- space attention ----------------
        layernorm_pack_kernel<<<(NTOK + 7) / 8, 256>>>(x, s_ln_g + i * D, s_ln_b + i * D, xnH, xnL);
        gemm128(xnH, xnL, wqsH + (size_t)i * 256 * QKVW, wqsL + (size_t)i * 256 * QKVW,
                nullptr, nullptr, qkv, NTOK, QKVW, 256);
        cls_attn_p1<<<dim3(NHEAD, CLSB), 256>>>(qkv, cpart);
        cls_attn_p2<<<NHEAD, 64>>>(cpart, atH, atL);
        space_flash_kernel<<<dim3(10, NGRP), 256, SMEM_F>>>(qkv, atH, atL);
        gemm64(atH, atL, wosH + (size_t)i * 256 * D, wosL + (size_t)i * 256 * D,
               s_out_b + i * D, x, x, NTOK, D, 256);

        // ---------------- GEGLU FF (geglu fused into FF1 epilogue) ----------------
        layernorm_pack_kernel<<<(NTOK + 7) / 8, 256>>>(x, f_ln_g + i * D, f_ln_b + i * D, xnH, xnL);
        gemm_geglu(xnH, xnL, w1H + (size_t)i * 256 * FF1, w1L + (size_t)i * 256 * FF1,
                   b1p + i * FF1, acH, acL, NTOK, FF1, 256);
        gemm64(acH, acL, w2H + (size_t)i * 1024 * D, w2L + (size_t)i * 1024 * D,
               f_b2 + i * D, x, x, NTOK, D, 1024);
    }

    // ---- final LN on cls + head ----
    layernorm_kernel<<<1, 256>>>(x, o_ln_g, o_ln_b, xn);
    head_kernel<<<1, 64>>>(xn, o_w, o_b, out);
}

// round 17
// speedup vs baseline: 1.0074x; 1.0074x over previous
#include <cuda_runtime.h>
#include <cuda_bf16.h>
#include <math.h>

namespace {

typedef unsigned int uint;

constexpr int NTOK  = 4801;
constexpr int D     = 512;
constexpr int QKVW  = 1536;
constexpr int NSP   = 1200;
constexpr int HALFN = 600;
constexpr int NKEY  = 601;
constexpr int NHEAD = 8;
constexpr int DH    = 64;
constexpr float ASCALE = 0.125f;
constexpr int FF1   = 4096;
constexpr int NPATCH= 4800;
constexpr int NGRP  = 64;
constexpr int CLSB  = 19;

// fp32 buffers
__device__ float g_x  [NTOK * D];
__device__ float g_xn [D];
__device__ float g_qkv[NTOK * QKVW];
__device__ float g_cpart[NHEAD * CLSB * 65];
__device__ float g_b1p[12 * FF1];

// packed bf16x2 hi/lo activations (pair along k)
__device__ uint g_xnH[NTOK * 256],  g_xnL[NTOK * 256];
__device__ uint g_atH[NTOK * 256],  g_atL[NTOK * 256];
__device__ uint g_acH[NTOK * 1024], g_acL[NTOK * 1024];
__device__ uint g_tkH[NPATCH * 384], g_tkL[NPATCH * 384];

// split weights [Kp][N] packed bf16x2 (pair along k), per layer contiguous
__device__ uint g_wqtH[12 * 256 * QKVW], g_wqtL[12 * 256 * QKVW];
__device__ uint g_wqsH[12 * 256 * QKVW], g_wqsL[12 * 256 * QKVW];
__device__ uint g_wotH[12 * 256 * D],    g_wotL[12 * 256 * D];
__device__ uint g_wosH[12 * 256 * D],    g_wosL[12 * 256 * D];
__device__ uint g_w1H [12 * 256 * FF1],  g_w1L [12 * 256 * FF1];   // column-permuted (u,g interleave)
__device__ uint g_w2H [12 * 1024 * D],   g_w2L [12 * 1024 * D];
__device__ uint g_wpH [384 * D],         g_wpL [384 * D];

__device__ __forceinline__ void split2(float x0, float x1, uint& hi, uint& lo) {
    __nv_bfloat16 h0 = __float2bfloat16(x0);
    __nv_bfloat16 h1 = __float2bfloat16(x1);
    __nv_bfloat16 l0 = __float2bfloat16(x0 - __bfloat162float(h0));
    __nv_bfloat16 l1 = __float2bfloat16(x1 - __bfloat162float(h1));
    __nv_bfloat162 H = __nv_bfloat162(h0, h1);
    __nv_bfloat162 L = __nv_bfloat162(l0, l1);
    hi = *reinterpret_cast<uint*>(&H);
    lo = *reinterpret_cast<uint*>(&L);
}

__device__ __forceinline__ void mma_bf16(float* acc, const uint* a, const uint* b) {
    asm volatile(
        "mma.sync.aligned.m16n8k16.row.col.f32.bf16.bf16.f32 "
        "{%0,%1,%2,%3}, {%4,%5,%6,%7}, {%8,%9}, {%0,%1,%2,%3};"
        : "+f"(acc[0]), "+f"(acc[1]), "+f"(acc[2]), "+f"(acc[3])
        : "r"(a[0]), "r"(a[1]), "r"(a[2]), "r"(a[3]), "r"(b[0]), "r"(b[1]));
}

__device__ __forceinline__ void ldsm4(uint& r0, uint& r1, uint& r2, uint& r3, uint addr) {
    asm volatile("ldmatrix.sync.aligned.m8n8.x4.shared.b16 {%0,%1,%2,%3}, [%4];"
                 : "=r"(r0), "=r"(r1), "=r"(r2), "=r"(r3) : "r"(addr));
}

__device__ __forceinline__ uint smem_u32(const void* p) {
    uint a;
    asm("{ .reg .u64 t; cvta.to.shared.u64 t, %1; cvt.u32.u64 %0, t; }" : "=r"(a) : "l"(p));
    return a;
}

// ================= GEMM: 3-stage cp.async, single sync per K-step =================
template <int MT>
struct GemmCfg {
    static constexpr int BM     = 32 * MT;
    static constexpr int OFF_AL = 640 * MT;
    static constexpr int OFF_BH = 1280 * MT;
    static constexpr int OFF_BL = 1280 * MT + 2176;
    static constexpr int STG_U  = 1280 * MT + 4352;
    static constexpr int SMEM   = 3 * STG_U * 4;
};
constexpr int SMEM_G128 = GemmCfg<4>::SMEM;
constexpr int SMEM_G64  = GemmCfg<2>::SMEM;

template <int MT, bool GEGLU>
__global__ __launch_bounds__(256, 2)
void bgemm_kernel(const uint* __restrict__ AH, const uint* __restrict__ AL,
                  const uint* __restrict__ BH, const uint* __restrict__ BL,
                  const float* __restrict__ bias, const float* __restrict__ resid,
                  float* __restrict__ C, uint* __restrict__ CH, uint* __restrict__ CL,
                  int M, int N, int Kp)
{
    using CF = GemmCfg<MT>;
    extern __shared__ uint dsm[];
    const uint sbase = smem_u32(dsm);
    const int tid  = threadIdx.x;
    const int lane = tid & 31;
    const int warp = tid >> 5;
    const int grp  = lane >> 2;
    const int qid  = lane & 3;
    const int wm   = (warp & 1) * (MT * 16);
    const int wn   = (warp >> 1) * 32;
    const int row0 = blockIdx.y * CF::BM;
    const int col0 = blockIdx.x * 128;

    float acc[MT][4][4];
#pragma unroll
    for (int mt = 0; mt < MT; mt++)
#pragma unroll
        for (int nt = 0; nt < 4; nt++)
#pragma unroll
            for (int e = 0; e < 4; e++) acc[mt][nt][e] = 0.f;

    auto load_stage = [&](int st, int kp0) {
        uint base = sbase + st * (CF::STG_U * 4);
#pragma unroll
        for (int u = 0; u < MT / 2; u++) {
            int idx = tid + u * 256;
            int r = idx >> 2, c4 = idx & 3;
            int gr = row0 + r;
            int sz = (gr < M) ? 16 : 0;
            size_t goff = (size_t)(gr < M ? gr : 0) * Kp + kp0 + c4 * 4;
            uint d = base + (r * 20 + c4 * 4) * 4;
            asm volatile("cp.async.cg.shared.global [%0], [%1], 16, %2;"
                         :: "r"(d), "l"(AH + goff), "r"(sz));
            asm volatile("cp.async.cg.shared.global [%0], [%1], 16, %2;"
                         :: "r"(d + CF::OFF_AL * 4), "l"(AL + goff), "r"(sz));
        }
#pragma unroll
        for (int u = 0; u < 2; u++) {
            int idx = tid + u * 256;
            int kr = idx >> 5, c4 = idx & 31;
            size_t goff = (size_t)(kp0 + kr) * N + col0 + c4 * 4;
            uint d = base + (CF::OFF_BH + kr * 136 + c4 * 4) * 4;
            asm volatile("cp.async.cg.shared.global [%0], [%1], 16;"
                         :: "r"(d), "l"(BH + goff));
            asm volatile("cp.async.cg.shared.global [%0], [%1], 16;"
                         :: "r"(d + (CF::OFF_BL - CF::OFF_BH) * 4), "l"(BL + goff));
        }
    };

    auto compute = [&](int st) {
        const uint* AsH = dsm + st * CF::STG_U;
        const uint* AsL = AsH + CF::OFF_AL;
        const uint* BsH = dsm + st * CF::STG_U + CF::OFF_BH;
        const uint* BsL = dsm + st * CF::STG_U + CF::OFF_BL;
#pragma unroll
        for (int kk = 0; kk < 2; kk++) {
            uint bhf[4][2], blf[4][2];
#pragma unroll
            for (int nt = 0; nt < 4; nt++) {
                int c = wn + nt * 8 + grp;
                bhf[nt][0] = BsH[(kk * 8 + qid    ) * 136 + c];
                bhf[nt][1] = BsH[(kk * 8 + qid + 4) * 136 + c];
                blf[nt][0] = BsL[(kk * 8 + qid    ) * 136 + c];
                blf[nt][1] = BsL[(kk * 8 + qid + 4) * 136 + c];
            }
#pragma unroll
            for (int mt = 0; mt < MT; mt++) {
                int r = wm + mt * 16;
                uint ah[4], al[4];
                ah[0] = AsH[(r + grp    ) * 20 + kk * 8 + qid    ];
                ah[1] = AsH[(r + grp + 8) * 20 + kk * 8 + qid    ];
                ah[2] = AsH[(r + grp    ) * 20 + kk * 8 + qid + 4];
                ah[3] = AsH[(r + grp + 8) * 20 + kk * 8 + qid + 4];
                al[0] = AsL[(r + grp    ) * 20 + kk * 8 + qid    ];
                al[1] = AsL[(r + grp + 8) * 20 + kk * 8 + qid    ];
                al[2] = AsL[(r + grp    ) * 20 + kk * 8 + qid + 4];
                al[3] = AsL[(r + grp + 8) * 20 + kk * 8 + qid + 4];
#pragma unroll
                for (int nt = 0; nt < 4; nt++) {
                    mma_bf16(acc[mt][nt], al, bhf[nt]);
                    mma_bf16(acc[mt][nt], ah, blf[nt]);
                    mma_bf16(acc[mt][nt], ah, bhf[nt]);
                }
            }
        }
    };

    const int nch = Kp / 16;
    load_stage(0, 0);
    asm volatile("cp.async.commit_group;" ::: "memory");
    load_stage(1, 16);
    asm volatile("cp.async.commit_group;" ::: "memory");
    for (int ch = 0; ch < nch; ch++) {
        if (ch + 1 < nch) asm volatile("cp.async.wait_group 1;" ::: "memory");
        else              asm volatile("cp.async.wait_group 0;" ::: "memory");
        __syncthreads();
        int nx = ch + 2;
        if (nx < nch) {
            load_stage(nx % 3, nx * 16);
            asm volatile("cp.async.commit_group;" ::: "memory");
        }
        compute(ch % 3);
    }

#pragma unroll
    for (int mt = 0; mt < MT; mt++) {
#pragma unroll
        for (int e2 = 0; e2 < 2; e2++) {
            int gr = row0 + wm + mt * 16 + grp + e2 * 8;
#pragma unroll
            for (int nt = 0; nt < 4; nt++) {
                int gc = col0 + wn + nt * 8 + qid * 2;
                float v0 = acc[mt][nt][e2 * 2 + 0];
                float v1 = acc[mt][nt][e2 * 2 + 1];
                if (GEGLU) {
                    v0 += bias[gc];
                    v1 += bias[gc + 1];
                    float ge = 0.5f * v1 * (1.f + erff(v1 * 0.70710678118654752f));
                    float act = v0 * ge;
                    float partner = __shfl_xor_sync(0xffffffffu, act, 1);
                    if (gr < M && (qid & 1) == 0) {
                        split2(act, partner,
                               CH[(size_t)gr * (N >> 2) + (gc >> 2)],
                               CL[(size_t)gr * (N >> 2) + (gc >> 2)]);
                    }
                } else {
                    if (gr < M) {
                        if (bias)  { v0 += bias[gc]; v1 += bias[gc + 1]; }
                        if (resid) {
                            v0 += resid[(size_t)gr * N + gc];
                            v1 += resid[(size_t)gr * N + gc + 1];
                        }
                        C[(size_t)gr * N + gc]     = v0;
                        C[(size_t)gr * N + gc + 1] = v1;
                    }
                }
            }
        }
    }
}

// ---------------------------------------------------------------- weight split prep (vectorized: 4 cols/thread)
__global__ void split_w_kernel(const float* __restrict__ W, uint* __restrict__ H,
                               uint* __restrict__ L, int Nq, long long totalq)
{
    long long idx = (long long)blockIdx.x * blockDim.x + threadIdx.x;
    if (idx >= totalq) return;
    long long kp = idx / Nq;
    int n4 = (int)(idx - kp * Nq) * 4;
    int N = Nq * 4;
    const float* r0 = W + (size_t)(2 * kp) * N + n4;
    float4 a = *reinterpret_cast<const float4*>(r0);
    float4 b = *reinterpret_cast<const float4*>(r0 + N);
    uint h0, l0, h1, l1, h2, l2, h3, l3;
    split2(a.x, b.x, h0, l0);
    split2(a.y, b.y, h1, l1);
    split2(a.z, b.z, h2, l2);
    split2(a.w, b.w, h3, l3);
    *reinterpret_cast<uint4*>(H + idx * 4) = make_uint4(h0, h1, h2, h3);
    *reinterpret_cast<uint4*>(L + idx * 4) = make_uint4(l0, l1, l2, l3);
}

// w1 split with u/g column interleave (vectorized: 4 output cols/thread)
// out col n -> orig col (n&1 ? 2048+(n>>1) : n>>1); quad n4..n4+3 reads cols {m,m+1} and {2048+m,2048+m+1}
__global__ void split_w1_kernel(const float* __restrict__ W, uint* __restrict__ H,
                                uint* __restrict__ L, long long totalq)
{
    long long idx = (long long)blockIdx.x * blockDim.x + threadIdx.x;
    if (idx >= totalq) return;
    long long kp = idx / 1024;           // FF1/4
    int q = (int)(idx - kp * 1024);
    int m = q * 2;
    const float* r0 = W + (size_t)(2 * kp) * FF1;
    const float* r1 = r0 + FF1;
    float2 u0 = *reinterpret_cast<const float2*>(r0 + m);
    float2 g0 = *reinterpret_cast<const float2*>(r0 + 2048 + m);
    float2 u1 = *reinterpret_cast<const float2*>(r1 + m);
    float2 g1 = *reinterpret_cast<const float2*>(r1 + 2048 + m);
    uint h0, l0, h1, l1, h2, l2, h3, l3;
    split2(u0.x, u1.x, h0, l0);   // out col n4   (u, col m)
    split2(g0.x, g1.x, h1, l1);   // out col n4+1 (g, col m)
    split2(u0.y, u1.y, h2, l2);   // out col n4+2 (u, col m+1)
    split2(g0.y, g1.y, h3, l3);   // out col n4+3 (g, col m+1)
    *reinterpret_cast<uint4*>(H + idx * 4) = make_uint4(h0, h1, h2, h3);
    *reinterpret_cast<uint4*>(L + idx * 4) = make_uint4(l0, l1, l2, l3);
}

__global__ void permute_b1_kernel(const float* __restrict__ B, float* __restrict__ O)
{
    int idx = blockIdx.x * blockDim.x + threadIdx.x;
    if (idx >= 12 * FF1) return;
    int l = idx >> 12, n = idx & 4095;
    int oc = (n & 1) ? (2048 + (n >> 1)) : (n >> 1);
    O[idx] = B[l * FF1 + oc];
}

// ---------------------------------------------------------------- patchify (packed out)
__global__ void patchify_kernel(const float* __restrict__ video,
                                uint* __restrict__ tH, uint* __restrict__ tL)
{
    int idx = blockIdx.x * blockDim.x + threadIdx.x;
    if (idx >= NPATCH * 384) return;
    int t = idx / 384, pp = idx % 384;
    int side = t / 2400;
    int r = t % 2400;
    int f = r / 600;
    int rr = r % 600;
    int ph = rr / 20;
    int pw = rr % 20;
    float v[2];
#pragma unroll
    for (int e = 0; e < 2; e++) {
        int pd = pp * 2 + e;
        int p1 = pd / 48;
        int rem = pd % 48;
        int p2 = rem / 3;
        int c  = rem % 3;
        int row = ph * 16 + p1;
        int col = side * 320 + pw * 16 + p2;
        v[e] = video[(((size_t)f * 3 + c) * 480 + row) * 640 + col];
    }
    split2(v[0], v[1], tH[idx], tL[idx]);
}

__global__ void addpos_kernel(float* __restrict__ x, const float* __restrict__ cls,
                              const float* __restrict__ pos)
{
    int idx = blockIdx.x * blockDim.x + threadIdx.x;
    if (idx >= NTOK * D) return;
    if (idx < D) x[idx] = cls[idx] + pos[idx];
    else         x[idx] += pos[idx];
}

// ---------------------------------------------------------------- LayerNorm (warp-per-row, packed out)
__global__ __launch_bounds__(256)
void layernorm_pack_kernel(const float* __restrict__ x, const float* __restrict__ g,
                           const float* __restrict__ b,
                           uint* __restrict__ oH, uint* __restrict__ oL)
{
    int warp = threadIdx.x >> 5, lane = threadIdx.x & 31;
    int row = blockIdx.x * 8 + warp;
    if (row >= NTOK) return;
    const float* xr = x + (size_t)row * D;

    float4 a[4];
#pragma unroll
    for (int k = 0; k < 4; k++)
        a[k] = *reinterpret_cast<const float4*>(xr + (k * 32 + lane) * 4);

    float s = 0.f;
#pragma unroll
    for (int k = 0; k < 4; k++) s += a[k].x + a[k].y + a[k].z + a[k].w;
#pragma unroll
    for (int o = 16; o; o >>= 1) s += __shfl_xor_sync(0xffffffffu, s, o);
    float mu = s * (1.f / 512.f);

    float v = 0.f;
#pragma unroll
    for (int k = 0; k < 4; k++) {
        float d0 = a[k].x - mu, d1 = a[k].y - mu, d2 = a[k].z - mu, d3 = a[k].w - mu;
        v += d0 * d0 + d1 * d1 + d2 * d2 + d3 * d3;
    }
#pragma unroll
    for (int o = 16; o; o >>= 1) v += __shfl_xor_sync(0xffffffffu, v, o);
    float rstd = rsqrtf(v * (1.f / 512.f) + 1e-5f);

#pragma unroll
    for (int k = 0; k < 4; k++) {
        int e4 = (k * 32 + lane) * 4;
        float4 gv = *reinterpret_cast<const float4*>(g + e4);
        float4 bv = *reinterpret_cast<const float4*>(b + e4);
        float y0 = (a[k].x - mu) * rstd * gv.x + bv.x;
        float y1 = (a[k].y - mu) * rstd * gv.y + bv.y;
        float y2 = (a[k].z - mu) * rstd * gv.z + bv.z;
        float y3 = (a[k].w - mu) * rstd * gv.w + bv.w;
        uint h0, l0, h1, l1;
        split2(y0, y1, h0, l0);
        split2(y2, y3, h1, l1);
        uint2 H = make_uint2(h0, h1), L = make_uint2(l0, l1);
        *reinterpret_cast<uint2*>(oH + (size_t)row * 256 + (e4 >> 1)) = H;
        *reinterpret_cast<uint2*>(oL + (size_t)row * 256 + (e4 >> 1)) = L;
    }
}

// ---------------------------------------------------------------- final LN (fp32, row 0)
__global__ void layernorm_kernel(const float* __restrict__ x, const float* __restrict__ g,
                                 const float* __restrict__ b, float* __restrict__ out)
{
    int tid = threadIdx.x;
    float x0 = x[tid], x1 = x[tid + 256];
    __shared__ float red[8];

    float s = x0 + x1;
#pragma unroll
    for (int o = 16; o; o >>= 1) s += __shfl_xor_sync(0xffffffffu, s, o);
    if ((tid & 31) == 0) red[tid >> 5] = s;
    __syncthreads();
    if (tid == 0) { float t = 0; for (int i = 0; i < 8; i++) t += red[i]; red[0] = t; }
    __syncthreads();
    float mu = red[0] * (1.f / 512.f);
    __syncthreads();

    float d0 = x0 - mu, d1 = x1 - mu;
    float v = d0 * d0 + d1 * d1;
#pragma unroll
    for (int o = 16; o; o >>= 1) v += __shfl_xor_sync(0xffffffffu, v, o);
    if ((tid & 31) == 0) red[tid >> 5] = v;
    __syncthreads();
    if (tid == 0) { float t = 0; for (int i = 0; i < 8; i++) t += red[i]; red[0] = t; }
    __syncthreads();
    float rstd = rsqrtf(red[0] * (1.f / 512.f) + 1e-5f);

    out[tid]       = d0 * rstd * g[tid] + b[tid];
    out[tid + 256] = d1 * rstd * g[tid + 256] + b[tid + 256];
}

// ---------------------------------------------------------------- cls attention phase 1 (split-K)
__global__ void cls_attn_p1(const float* __restrict__ qkv, float* __restrict__ cpart)
{
    int h = blockIdx.x, blk = blockIdx.y;
    int tid = threadIdx.x;
    __shared__ float qs[DH];
    __shared__ float sl[256];
    __shared__ float red[8];
    __shared__ float part[4][DH];

    if (tid < DH) qs[tid] = ASCALE * qkv[h * DH + tid];
    __syncthreads();

    int tok = blk * 256 + tid;
    float e = 0.f;
    if (tok < NTOK) {
        const float* kb = qkv + (size_t)tok * QKVW + 512 + h * DH;
        float s = 0.f;
#pragma unroll
        for (int d4 = 0; d4 < DH; d4 += 4) {
            float4 kv = *reinterpret_cast<const float4*>(kb + d4);
            s += qs[d4] * kv.x + qs[d4 + 1] * kv.y + qs[d4 + 2] * kv.z + qs[d4 + 3] * kv.w;
        }
        e = __expf(s);
    }
    sl[tid] = e;
    float esum = e;
#pragma unroll
    for (int o = 16; o; o >>= 1) esum += __shfl_xor_sync(0xffffffffu, esum, o);
    if ((tid & 31) == 0) red[tid >> 5] = esum;
    __syncthreads();

    int gi = tid >> 6, d = tid & 63;
    float acc = 0.f;
    for (int jj = gi; jj < 256; jj += 4) {
        int t2 = blk * 256 + jj;
        if (t2 < NTOK) acc += sl[jj] * qkv[(size_t)t2 * QKVW + 1024 + h * DH + d];
    }
    part[gi][d] = acc;
    __syncthreads();

    if (tid < DH)
        cpart[(h * CLSB + blk) * 65 + tid] =
            part[0][tid] + part[1][tid] + part[2][tid] + part[3][tid];
    if (tid == 0) {
        float t = 0.f;
        for (int i = 0; i < 8; i++) t += red[i];
        cpart[(h * CLSB + blk) * 65 + 64] = t;
    }
}

// ---------------------------------------------------------------- cls attention phase 2 (standalone, space path)
__global__ void cls_attn_p2(const float* __restrict__ cpart,
                            uint* __restrict__ aH, uint* __restrict__ aL)
{
    int h = blockIdx.x;
    int tid = threadIdx.x;  // 64
    __shared__ float o[DH];
    float acc = 0.f, den = 0.f;
    for (int b = 0; b < CLSB; b++) {
        acc += cpart[(h * CLSB + b) * 65 + tid];
        den += cpart[(h * CLSB + b) * 65 + 64];
    }
    o[tid] = acc / den;
    __syncthreads();
    if (tid < 32) split2(o[2 * tid], o[2 * tid + 1], aH[h * 32 + tid], aL[h * 32 + tid]);
}

// ---------------------------------------------------------------- time attention (+fused cls p2 in last block)
__global__ void time_attn_kernel(const float* __restrict__ qkv, const float* __restrict__ cpart,
                                 uint* __restrict__ aH, uint* __restrict__ aL)
{
    if (blockIdx.x == 4800) {
        // fused cls phase 2: thread = (head, dim-pair); same arithmetic as cls_attn_p2
        int h = threadIdx.x >> 5, t = threadIdx.x & 31;
        float a0 = 0.f, a1 = 0.f, den = 0.f;
        for (int b = 0; b < CLSB; b++) {
            const float* cp = cpart + (h * CLSB + b) * 65;
            a0 += cp[2 * t];
            a1 += cp[2 * t + 1];
            den += cp[64];
        }
        split2(a0 / den, a1 / den, aH[h * 32 + t], aL[h * 32 + t]);
        return;
    }

    int w = (blockIdx.x * blockDim.x + threadIdx.x) >> 5;
    int lane = threadIdx.x & 31;
    int h = w / (NSP * 4);
    int rem = w % (NSP * 4);
    int nn = rem / 4;
    int f  = rem % 4;
    int qt = 1 + f * NSP + nn;

    const float* qb = qkv + (size_t)qt * QKVW + h * DH;
    float q0 = ASCALE * qb[2 * lane], q1 = ASCALE * qb[2 * lane + 1];

    int kt[5] = {0, 1 + nn, 1 + NSP + nn, 1 + 2 * NSP + nn, 1 + 3 * NSP + nn};
    float lg[5];
#pragma unroll
    for (int j = 0; j < 5; j++) {
        const float* kb = qkv + (size_t)kt[j] * QKVW + 512 + h * DH;
        float p = q0 * kb[2 * lane] + q1 * kb[2 * lane + 1];
#pragma unroll
        for (int o = 16; o; o >>= 1) p += __shfl_xor_sync(0xffffffffu, p, o);
        lg[j] = p;
    }
    float m = lg[0];
#pragma unroll
    for (int j = 1; j < 5; j++) m = fmaxf(m, lg[j]);
    float e[5], s = 0.f;
#pragma unroll
    for (int j = 0; j < 5; j++) { e[j] = expf(lg[j] - m); s += e[j]; }
    float inv = 1.f / s;

    float o0 = 0.f, o1 = 0.f;
#pragma unroll
    for (int j = 0; j < 5; j++) {
        const float* vb = qkv + (size_t)kt[j] * QKVW + 1024 + h * DH;
        float p = e[j] * inv;
        o0 += p * vb[2 * lane];
        o1 += p * vb[2 * lane + 1];
    }
    split2(o0, o1, aH[(size_t)qt * 256 + h * 32 + lane], aL[(size_t)qt * 256 + h * 32 + lane]);
}

// ---------------------------------------------------------------- fused space attention (flash)
constexpr uint OQ_H = 0,     OQ_L = 2304;
constexpr uint OK_H = 4608,  OK_L = 6912;
constexpr uint OV_H = 9216,  OV_L = 11520;
constexpr uint OP_H = 13824, OP_L = 16128;
constexpr uint ODEN = 18432;
constexpr int  SMEM_F = (18432 + 128) * 4;

__global__ __launch_bounds__(256)
void space_flash_kernel(const float* __restrict__ qkv,
                        uint* __restrict__ aH, uint* __restrict__ aL)
{
    extern __shared__ uint sm[];
    float* den = reinterpret_cast<float*>(sm + ODEN);
    const uint sbase = smem_u32(sm);

    int g = blockIdx.y;
    int h = g >> 3, f = (g >> 1) & 3, half = g & 1;
    int i0 = blockIdx.x * 64;
    int tid = threadIdx.x;
    int lane = tid & 31, warp = tid >> 5;
    int grp = lane >> 2, qid = lane & 3;
    int wm = (warp & 3) * 16;
    int wn = (warp >> 2) * 32;
    const int subA_row = ((lane >> 3) & 1) * 8 + (lane & 7);
    const int subA_col = ((lane >> 4) & 1) * 4;
    const int subB_row = ((lane >> 4) & 1) * 8 + (lane & 7);
    const int subB_col = ((lane >> 3) & 1) * 4;
    const int kbase = 1 + f * NSP + (1 - half) * HALFN;

#pragma unroll
    for (int u = 0; u < 8; u++) {
        int idx = tid + u * 256;
        int r = idx >> 5, dp = idx & 31;
        int i = i0 + r;
        float2 qv = make_float2(0.f, 0.f);
        if (i < HALFN) {
            int qt = 1 + f * NSP + half * HALFN + i;
            qv = *reinterpret_cast<const float2*>(qkv + (size_t)qt * QKVW + h * DH + 2 * dp);
        }
        split2(ASCALE * qv.x, ASCALE * qv.y, sm[OQ_H + r * 36 + dp], sm[OQ_L + r * 36 + dp]);
    }

    float oacc[4][4];
#pragma unroll
    for (int nt = 0; nt < 4; nt++)
#pragma unroll
        for (int e = 0; e < 4; e++) oacc[nt][e] = 0.f;
    float dsum[2] = {0.f, 0.f};

    for (int jt = 0; jt < 10; jt++) {
        int j0 = jt * 64;
#pragma unroll
        for (int u = 0; u < 8; u++) {
            int idx = tid + u * 256;
            int r = idx >> 5, dp = idx & 31;
            int j = j0 + r;
            float2 kv = make_float2(0.f, 0.f);
            if (j < NKEY) {
                int kt = j ? (kbase + j - 1) : 0;
                kv = *reinterpret_cast<const float2*>(qkv + (size_t)kt * QKVW + 512 + h * DH + 2 * dp);
            }
            split2(kv.x, kv.y, sm[OK_H + r * 36 + dp], sm[OK_L + r * 36 + dp]);
        }
#pragma unroll
        for (int u = 0; u < 8; u++) {
            int idx = tid + u * 256;
            int d = idx & 63, jp = idx >> 6;
            int j1 = j0 + 2 * jp, j2 = j1 + 1;
            float v0 = 0.f, v1 = 0.f;
            if (j1 < NKEY) {
                int kt = j1 ? (kbase + j1 - 1) : 0;
                v0 = qkv[(size_t)kt * QKVW + 1024 + h * DH + d];
            }
            if (j2 < NKEY) {
                int kt = kbase + j2 - 1;
                v1 = qkv[(size_t)kt * QKVW + 1024 + h * DH + d];
            }
            split2(v0, v1, sm[OV_H + d * 36 + jp], sm[OV_L + d * 36 + jp]);
        }
        __syncthreads();

        float facc[4][4];
#pragma unroll
        for (int nt = 0; nt < 4; nt++)
#pragma unroll
            for (int e = 0; e < 4; e++) facc[nt][e] = 0.f;
#pragma unroll
        for (int kk = 0; kk < 4; kk++) {
            uint ah[4], al[4];
            uint aaddr = sbase + (OQ_H + (wm + subA_row) * 36 + kk * 8 + subA_col) * 4;
            ldsm4(ah[0], ah[1], ah[2], ah[3], aaddr);
            ldsm4(al[0], al[1], al[2], al[3], aaddr + (OQ_L - OQ_H) * 4);
            uint bh[4][2], bl[4][2];
#pragma unroll
            for (int p = 0; p < 2; p++) {
                uint baddr = sbase + (OK_H + (wn + p * 16 + subB_row) * 36 + kk * 8 + subB_col) * 4;
                ldsm4(bh[2 * p][0], bh[2 * p][1], bh[2 * p + 1][0], bh[2 * p + 1][1], baddr);
                ldsm4(bl[2 * p][0], bl[2 * p][1], bl[2 * p + 1][0], bl[2 * p + 1][1],
                      baddr + (OK_L - OK_H) * 4);
            }
#pragma unroll
            for (int nt = 0; nt < 4; nt++) {
                mma_bf16(facc[nt], al, bh[nt]);
                mma_bf16(facc[nt], ah, bl[nt]);
                mma_bf16(facc[nt], ah, bh[nt]);
            }
        }
#pragma unroll
        for (int e2 = 0; e2 < 2; e2++) {
            int row = wm + grp + e2 * 8;
#pragma unroll
            for (int nt = 0; nt < 4; nt++) {
                int jl = wn + nt * 8 + qid * 2;
                int jg = j0 + jl;
                float p0 = (jg     < NKEY) ? __expf(facc[nt][e2 * 2 + 0]) : 0.f;
                float p1 = (jg + 1 < NKEY) ? __expf(facc[nt][e2 * 2 + 1]) : 0.f;
                dsum[e2] += p0 + p1;
                split2(p0, p1, sm[OP_H + row * 36 + (jl >> 1)], sm[OP_L + row * 36 + (jl >> 1)]);
            }
        }
        __syncthreads();

#pragma unroll
        for (int kk = 0; kk < 4; kk++) {
            uint ah[4], al[4];
            uint aaddr = sbase + (OP_H + (wm + subA_row) * 36 + kk * 8 + subA_col) * 4;
            ldsm4(ah[0], ah[1], ah[2], ah[3], aaddr);
            ldsm4(al[0], al[1], al[2], al[3], aaddr + (OP_L - OP_H) * 4);
            uint bh[4][2], bl[4][2];
#pragma unroll
            for (int p = 0; p < 2; p++) {
                uint baddr = sbase + (OV_H + (wn + p * 16 + subB_row) * 36 + kk * 8 + subB_col) * 4;
                ldsm4(bh[2 * p][0], bh[2 * p][1], bh[2 * p + 1][0], bh[2 * p + 1][1], baddr);
                ldsm4(bl[2 * p][0], bl[2 * p][1], bl[2 * p + 1][0], bl[2 * p + 1][1],
                      baddr + (OV_L - OV_H) * 4);
            }
#pragma unroll
            for (int nt = 0; nt < 4; nt++) {
                mma_bf16(oacc[nt], al, bh[nt]);
                mma_bf16(oacc[nt], ah, bl[nt]);
                mma_bf16(oacc[nt], ah, bh[nt]);
            }
        }
        __syncthreads();
    }

#pragma unroll
    for (int e2 = 0; e2 < 2; e2++) {
        float v = dsum[e2];
        v += __shfl_xor_sync(0xffffffffu, v, 1);
        v += __shfl_xor_sync(0xffffffffu, v, 2);
        if (qid == 0) den[(warp >> 2) * 64 + wm + grp + e2 * 8] = v;
    }
    __syncthreads();

#pragma unroll
    for (int e2 = 0; e2 < 2; e2++) {
        int row = wm + grp + e2 * 8;
        int i = i0 + row;
        if (i >= HALFN) continue;
        float inv = 1.f / (den[row] + den[64 + row]);
        int qt = 1 + f * NSP + half * HALFN + i;
#pragma unroll
        for (int nt = 0; nt < 4; nt++) {
            int dp = ((wn + nt * 8) >> 1) + qid;
            split2(oacc[nt][e2 * 2 + 0] * inv, oacc[nt][e2 * 2 + 1] * inv,
                   aH[(size_t)qt * 256 + h * 32 + dp], aL[(size_t)qt * 256 + h * 32 + dp]);
        }
    }
}

// ---------------------------------------------------------------- head
__global__ void head_kernel(const float* __restrict__ xn, const float* __restrict__ ow,
                            const float* __restrict__ ob, float* __restrict__ out)
{
    int tid = threadIdx.x;
    if (tid >= 60) return;
    float s = ob[tid];
    for (int d = 0; d < D; d++) s += xn[d] * ow[d * 60 + tid];
    out[tid] = s;
}

}  // namespace

extern "C" void kernel_launch(void* const* d_in, const int* in_sizes, int n_in,
                              void* d_out, int out_size)
{
    const float* video   = (const float*)d_in[0];
    const float* patch_w = (const float*)d_in[1];
    const float* patch_b = (const float*)d_in[2];
    const float* pos_emb = (const float*)d_in[3];
    const float* cls_tok = (const float*)d_in[4];
    const float* t_ln_g  = (const float*)d_in[5];
    const float* t_ln_b  = (const float*)d_in[6];
    const float* t_qkv_w = (const float*)d_in[7];
    const float* t_out_w = (const float*)d_in[8];
    const float* t_out_b = (const float*)d_in[9];
    const float* s_ln_g  = (const float*)d_in[10];
    const float* s_ln_b  = (const float*)d_in[11];
    const float* s_qkv_w = (const float*)d_in[12];
    const float* s_out_w = (const float*)d_in[13];
    const float* s_out_b = (const float*)d_in[14];
    const float* f_ln_g  = (const float*)d_in[15];
    const float* f_ln_b  = (const float*)d_in[16];
    const float* f_w1    = (const float*)d_in[17];
    const float* f_b1    = (const float*)d_in[18];
    const float* f_w2    = (const float*)d_in[19];
    const float* f_b2    = (const float*)d_in[20];
    const float* o_ln_g  = (const float*)d_in[21];
    const float* o_ln_b  = (const float*)d_in[22];
    const float* o_w     = (const float*)d_in[23];
    const float* o_b     = (const float*)d_in[24];
    float* out = (float*)d_out;

    cudaFuncSetAttribute(bgemm_kernel<4, false>, cudaFuncAttributeMaxDynamicSharedMemorySize, SMEM_G128);
    cudaFuncSetAttribute(bgemm_kernel<4, true>,  cudaFuncAttributeMaxDynamicSharedMemorySize, SMEM_G128);
    cudaFuncSetAttribute(bgemm_kernel<2, false>, cudaFuncAttributeMaxDynamicSharedMemorySize, SMEM_G64);
    cudaFuncSetAttribute(space_flash_kernel, cudaFuncAttributeMaxDynamicSharedMemorySize, SMEM_F);

    float *x, *xn, *qkv, *cpart, *b1p;
    cudaGetSymbolAddress((void**)&x,     g_x);
    cudaGetSymbolAddress((void**)&xn,    g_xn);
    cudaGetSymbolAddress((void**)&qkv,   g_qkv);
    cudaGetSymbolAddress((void**)&cpart, g_cpart);
    cudaGetSymbolAddress((void**)&b1p,   g_b1p);

    uint *xnH, *xnL, *atH, *atL, *acH, *acL, *tkH, *tkL;
    cudaGetSymbolAddress((void**)&xnH, g_xnH); cudaGetSymbolAddress((void**)&xnL, g_xnL);
    cudaGetSymbolAddress((void**)&atH, g_atH); cudaGetSymbolAddress((void**)&atL, g_atL);
    cudaGetSymbolAddress((void**)&acH, g_acH); cudaGetSymbolAddress((void**)&acL, g_acL);
    cudaGetSymbolAddress((void**)&tkH, g_tkH); cudaGetSymbolAddress((void**)&tkL, g_tkL);

    uint *wqtH, *wqtL, *wqsH, *wqsL, *wotH, *wotL, *wosH, *wosL, *w1H, *w1L, *w2H, *w2L, *wpH, *wpL;
    cudaGetSymbolAddress((void**)&wqtH, g_wqtH); cudaGetSymbolAddress((void**)&wqtL, g_wqtL);
    cudaGetSymbolAddress((void**)&wqsH, g_wqsH); cudaGetSymbolAddress((void**)&wqsL, g_wqsL);
    cudaGetSymbolAddress((void**)&wotH, g_wotH); cudaGetSymbolAddress((void**)&wotL, g_wotL);
    cudaGetSymbolAddress((void**)&wosH, g_wosH); cudaGetSymbolAddress((void**)&wosL, g_wosL);
    cudaGetSymbolAddress((void**)&w1H,  g_w1H);  cudaGetSymbolAddress((void**)&w1L,  g_w1L);
    cudaGetSymbolAddress((void**)&w2H,  g_w2H);  cudaGetSymbolAddress((void**)&w2L,  g_w2L);
    cudaGetSymbolAddress((void**)&wpH,  g_wpH);  cudaGetSymbolAddress((void**)&wpL,  g_wpL);

    auto splitw = [&](const float* W, uint* H, uint* L, long long Kp_total, int N) {
        long long totalq = Kp_total * (N / 4);
        int blocks = (int)((totalq + 255) / 256);
        split_w_kernel<<<blocks, 256>>>(W, H, L, N / 4, totalq);
    };

    splitw(t_qkv_w, wqtH, wqtL, 12LL * 256, QKVW);
    splitw(s_qkv_w, wqsH, wqsL, 12LL * 256, QKVW);
    splitw(t_out_w, wotH, wotL, 12LL * 256, D);
    splitw(s_out_w, wosH, wosL, 12LL * 256, D);
    {
        long long totalq = 12LL * 256 * (FF1 / 4);
        split_w1_kernel<<<(int)((totalq + 255) / 256), 256>>>(f_w1, w1H, w1L, totalq);
        permute_b1_kernel<<<(12 * FF1 + 255) / 256, 256>>>(f_b1, b1p);
    }
    splitw(f_w2,    w2H,  w2L,  12LL * 1024, D);
    splitw(patch_w, wpH,  wpL,  384LL, D);

    auto gemm128 = [&](const uint* AH, const uint* AL, const uint* BH, const uint* BL,
                       const float* bias, const float* resid, float* C, int M, int N, int Kp) {
        dim3 grid(N / 128, (M + 127) / 128);
        bgemm_kernel<4, false><<<grid, 256, SMEM_G128>>>(AH, AL, BH, BL, bias, resid, C,
                                                         nullptr, nullptr, M, N, Kp);
    };
    auto gemm64 = [&](const uint* AH, const uint* AL, const uint* BH, const uint* BL,
                      const float* bias, const float* resid, float* C, int M, int N, int Kp) {
        dim3 grid(N / 128, (M + 63) / 64);
        bgemm_kernel<2, false><<<grid, 256, SMEM_G64>>>(AH, AL, BH, BL, bias, resid, C,
                                                        nullptr, nullptr, M, N, Kp);
    };
    auto gemm_geglu = [&](const uint* AH, const uint* AL, const uint* BH, const uint* BL,
                          const float* bias, uint* CH, uint* CL, int M, int N, int Kp) {
        dim3 grid(N / 128, (M + 127) / 128);
        bgemm_kernel<4, true><<<grid, 256, SMEM_G128>>>(AH, AL, BH, BL, bias, nullptr, nullptr,
                                                        CH, CL, M, N, Kp);
    };

    // ---- patch embed + pos + cls ----
    patchify_kernel<<<(NPATCH * 384 + 255) / 256, 256>>>(video, tkH, tkL);
    gemm64(tkH, tkL, wpH, wpL, patch_b, nullptr, x + D, NPATCH, D, 384);
    addpos_kernel<<<(NTOK * D + 255) / 256, 256>>>(x, cls_tok, pos_emb);

    for (int i = 0; i < 12; i++) {
        // ---------------- time attention ----------------
        layernorm_pack_kernel<<<(NTOK + 7) / 8, 256>>>(x, t_ln_g + i * D, t_ln_b + i * D, xnH, xnL);
        gemm128(xnH, xnL, wqtH + (size_t)i * 256 * QKVW, wqtL + (size_t)i * 256 * QKVW,
                nullptr, nullptr, qkv, NTOK, QKVW, 256);
        cls_attn_p1<<<dim3(NHEAD, CLSB), 256>>>(qkv, cpart);
        time_attn_kernel<<<4801, 256>>>(qkv, cpart, atH, atL);   // block 4800 = fused cls p2
        gemm64(atH, atL, wotH + (size_t)i * 256 * D, wotL + (size_t)i * 256 * D,
               t_out_b + i * D, x, x, NTOK, D, 256);

        // ---------------- space attention ----------------
        layernorm_pack_kernel<<<(NTOK + 7) / 8, 256>>>(x, s_ln_g + i * D, s_ln_b + i * D, xnH, xnL);
        gemm128(xnH, xnL, wqsH + (size_t)i * 256 * QKVW, wqsL + (size_t)i * 256 * QKVW,
                nullptr, nullptr, qkv, NTOK, QKVW, 256);
        cls_attn_p1<<<dim3(NHEAD, CLSB), 256>>>(qkv, cpart);
        cls_attn_p2<<<NHEAD, 64>>>(cpart, atH, atL);
        space_flash_kernel<<<dim3(10, NGRP), 256, SMEM_F>>>(qkv, atH, atL);
        gemm64(atH, atL, wosH + (size_t)i * 256 * D, wosL + (size_t)i * 256 * D,
               s_out_b + i * D, x, x, NTOK, D, 256);

        // ---------------- GEGLU FF (geglu fused into FF1 epilogue) ----------------
        layernorm_pack_kernel<<<(NTOK + 7) / 8, 256>>>(x, f_ln_g + i * D, f_ln_b + i * D, xnH, xnL);
        gemm_geglu(xnH, xnL, w1H + (size_t)i * 256 * FF1, w1L + (size_t)i * 256 * FF1,
                   b1p + i * FF1, acH, acL, NTOK, FF1, 256);
        gemm64(acH, acL, w2H + (size_t)i * 1024 * D, w2L + (size_t)i * 1024 * D,
               f_b2 + i * D, x, x, NTOK, D, 1024);
    }

    // ---- final LN on cls + head ----
    layernorm_kernel<<<1, 256>>>(x, o_ln_g, o_ln_b, xn);
    head_kernel<<<1, 64>>>(xn, o_w, o_b, out);
}